// round 1
// baseline (speedup 1.0000x reference)
#include <cuda_runtime.h>
#include <math.h>

#define NN 50000
#define EE 400000
#define GG 64
#define FIN 16
#define HID 128
#define HEADS 4
#define C1 512   // HEADS*HID

// ---------------- scratch (static device memory; no allocs) ----------------
__device__ float    g_h1[NN * C1];        // x@W1               102.4 MB
__device__ float    g_out1[NN * C1];      // layer1 aggregated  102.4 MB
__device__ float    g_h2[NN * HID];       // hin@W2              25.6 MB
__device__ float    g_out2[NN * HID];     // layer2 aggregated   25.6 MB
__device__ float    g_as1[NN * HEADS], g_ad1[NN * HEADS];
__device__ float    g_vs1[NN * HEADS];    // self-loop logit, then self exp
__device__ float    g_den1[NN * HEADS];
__device__ unsigned g_m1[NN * HEADS];     // monotone-key max
__device__ float    g_ex1[EE * HEADS];    // edge logit, then exp
__device__ float    g_as2[NN], g_ad2[NN], g_vs2[NN], g_den2[NN];
__device__ unsigned g_m2[NN];
__device__ float    g_ex2[EE];
__device__ float    g_Ws1[FIN * HEADS], g_Wd1[FIN * HEADS];
__device__ float    g_w2s[C1], g_w2d[C1];
__device__ float    g_pool[GG * HID];
__device__ float    g_cnt[GG];

// ---------------- helpers ----------------
__device__ __forceinline__ float leaky(float x) { return x > 0.f ? x : 0.2f * x; }
__device__ __forceinline__ float eluf(float x)  { return x > 0.f ? x : expm1f(x); }

// monotone float<->uint key (order preserving) for atomicMax
__device__ __forceinline__ unsigned fkey(float f) {
    unsigned b = __float_as_uint(f);
    return (b & 0x80000000u) ? ~b : (b | 0x80000000u);
}
__device__ __forceinline__ float funkey(unsigned k) {
    return (k & 0x80000000u) ? __uint_as_float(k ^ 0x80000000u) : __uint_as_float(~k);
}

__device__ __forceinline__ void red_add_v4(float* p, float a, float b, float c, float d) {
    asm volatile("red.global.add.v4.f32 [%0], {%1,%2,%3,%4};"
                 :: "l"(p), "f"(a), "f"(b), "f"(c), "f"(d) : "memory");
}

// ---------------- K0: fold attention vectors into weights, zero pool ----------------
__global__ void k_prep(const float* __restrict__ W1, const float* __restrict__ as1,
                       const float* __restrict__ ad1, const float* __restrict__ W2,
                       const float* __restrict__ as2, const float* __restrict__ ad2) {
    int t = threadIdx.x;
    if (t < FIN * HEADS) {
        int k = t >> 2, h = t & 3;
        float s = 0.f, d = 0.f;
        for (int c = 0; c < HID; c++) {
            float w = W1[k * C1 + h * HID + c];
            s += w * as1[h * HID + c];
            d += w * ad1[h * HID + c];
        }
        g_Ws1[t] = s; g_Wd1[t] = d;
    }
    for (int i = t; i < C1; i += blockDim.x) {
        float s = 0.f, d = 0.f;
        for (int c = 0; c < HID; c++) {
            float w = W2[i * HID + c];
            s += w * as2[c];
            d += w * ad2[c];
        }
        g_w2s[i] = s; g_w2d[i] = d;
    }
    for (int i = t; i < GG * HID; i += blockDim.x) g_pool[i] = 0.f;
    if (t < GG) g_cnt[t] = 0.f;
}

// ---------------- K1: h1 = x @ W1  (8 rows/block, 512 threads = one col each) ----------------
__global__ void k_gemm1(const float* __restrict__ x, const float* __restrict__ W1) {
    __shared__ float sx[8][FIN];
    int t = threadIdx.x;
    int row0 = blockIdx.x * 8;
    if (t < 8 * FIN) {
        int r = t >> 4, k = t & 15;
        sx[r][k] = x[(row0 + r) * FIN + k];
    }
    __syncthreads();
    float w[FIN];
#pragma unroll
    for (int k = 0; k < FIN; k++) w[k] = W1[k * C1 + t];
#pragma unroll
    for (int r = 0; r < 8; r++) {
        float a = 0.f;
#pragma unroll
        for (int k = 0; k < FIN; k++) a += sx[r][k] * w[k];
        g_h1[(row0 + r) * C1 + t] = a;
    }
}

// ---------------- K2: per-node attention logits layer1 + init max ----------------
__global__ void k_att1(const float* __restrict__ x) {
    __shared__ float ws[FIN * HEADS], wd[FIN * HEADS];
    int t = threadIdx.x;
    if (t < FIN * HEADS) { ws[t] = g_Ws1[t]; wd[t] = g_Wd1[t]; }
    __syncthreads();
    int n = blockIdx.x * blockDim.x + t;
    if (n >= NN) return;
    float xr[FIN];
    const float4* xp = (const float4*)(x + n * FIN);
#pragma unroll
    for (int i = 0; i < 4; i++) {
        float4 v = xp[i];
        xr[i * 4 + 0] = v.x; xr[i * 4 + 1] = v.y; xr[i * 4 + 2] = v.z; xr[i * 4 + 3] = v.w;
    }
#pragma unroll
    for (int h = 0; h < HEADS; h++) {
        float s = 0.f, d = 0.f;
#pragma unroll
        for (int k = 0; k < FIN; k++) { s += xr[k] * ws[k * 4 + h]; d += xr[k] * wd[k * 4 + h]; }
        g_as1[n * 4 + h] = s;
        g_ad1[n * 4 + h] = d;
        float v = leaky(s + d);            // self-loop logit
        g_vs1[n * 4 + h] = v;
        g_m1[n * 4 + h] = fkey(v);
    }
}

// ---------------- K3: edge max pass (layer1) ----------------
__global__ void k_max1(const int* __restrict__ src, const int* __restrict__ dst) {
    int i = blockIdx.x * blockDim.x + threadIdx.x;
    if (i >= EE * HEADS) return;
    int e = i >> 2, h = i & 3;
    int s = src[e], d = dst[e];
    float v = leaky(g_as1[s * 4 + h] + g_ad1[d * 4 + h]);
    g_ex1[i] = v;
    atomicMax(&g_m1[d * 4 + h], fkey(v));
}

// ---------------- K4: denom init from self loops (layer1) ----------------
__global__ void k_den1(void) {
    int i = blockIdx.x * blockDim.x + threadIdx.x;
    if (i >= NN * HEADS) return;
    float m = funkey(g_m1[i]);
    float exs = expf(g_vs1[i] - m);
    g_den1[i] = exs;
    g_vs1[i] = exs;   // now holds self-loop exp
}

// ---------------- K5: edge exp + denom accumulation (layer1) ----------------
__global__ void k_exp1(const int* __restrict__ dst) {
    int i = blockIdx.x * blockDim.x + threadIdx.x;
    if (i >= EE * HEADS) return;
    int e = i >> 2, h = i & 3;
    int d = dst[e];
    float ex = expf(g_ex1[i] - funkey(g_m1[d * 4 + h]));
    g_ex1[i] = ex;
    atomicAdd(&g_den1[d * 4 + h], ex);
}

// ---------------- K6: out1 init with self-loop contribution ----------------
__global__ void k_out1init(void) {
    int t = threadIdx.x;
    int n = blockIdx.x * 2 + (t >> 7);
    int c4 = t & 127;
    int h = c4 >> 5;
    float a = g_vs1[n * 4 + h] / g_den1[n * 4 + h];
    float4 v = *(const float4*)&g_h1[n * C1 + c4 * 4];
    v.x *= a; v.y *= a; v.z *= a; v.w *= a;
    *(float4*)&g_out1[n * C1 + c4 * 4] = v;
}

// ---------------- K7: edge scatter-aggregate layer1 (2 edges/block, 128 thr/edge) -------
__global__ void k_scatter1(const int* __restrict__ src, const int* __restrict__ dst) {
    int t = threadIdx.x;
    int e = blockIdx.x * 2 + (t >> 7);
    if (e >= EE) return;
    int c4 = t & 127;
    int h = c4 >> 5;
    int s = src[e], d = dst[e];
    float a = g_ex1[e * 4 + h] / g_den1[d * 4 + h];
    float4 v = *(const float4*)&g_h1[s * C1 + c4 * 4];
    red_add_v4(&g_out1[d * C1 + c4 * 4], a * v.x, a * v.y, a * v.z, a * v.w);
}

// ---------------- K8: h2 = elu(out1 + b1) @ W2  (tiled SIMT GEMM 64x128x16) ----------------
__global__ void k_gemm2(const float* __restrict__ b1, const float* __restrict__ W2) {
    __shared__ float As[16 * 65];   // [k][m], padded
    __shared__ float Bs[16 * 128];  // [k][c]
    int t = threadIdx.x;
    int tx = t & 31;        // col group: cols tx*4..tx*4+3
    int ty = t >> 5;        // row group: rows ty*8..ty*8+7
    int row0 = blockIdx.x * 64;
    float acc[8][4];
#pragma unroll
    for (int i = 0; i < 8; i++)
#pragma unroll
        for (int j = 0; j < 4; j++) acc[i][j] = 0.f;

    for (int kt = 0; kt < C1; kt += 16) {
        // load A tile with fused elu(out1 + b1)
#pragma unroll
        for (int l = 0; l < 4; l++) {
            int idx = t + l * 256;
            int m = idx >> 4, k = idx & 15;
            int row = row0 + m;
            float v = 0.f;
            if (row < NN) {
                v = g_out1[row * C1 + kt + k] + b1[kt + k];
                v = eluf(v);
            }
            As[k * 65 + m] = v;
        }
        // load B tile
#pragma unroll
        for (int l = 0; l < 8; l++) {
            int idx = t + l * 256;
            int k = idx >> 7, c = idx & 127;
            Bs[k * 128 + c] = W2[(kt + k) * HID + c];
        }
        __syncthreads();
#pragma unroll
        for (int k = 0; k < 16; k++) {
            float4 bv = *(const float4*)&Bs[k * 128 + tx * 4];
#pragma unroll
            for (int i = 0; i < 8; i++) {
                float av = As[k * 65 + ty * 8 + i];
                acc[i][0] += av * bv.x;
                acc[i][1] += av * bv.y;
                acc[i][2] += av * bv.z;
                acc[i][3] += av * bv.w;
            }
        }
        __syncthreads();
    }
#pragma unroll
    for (int i = 0; i < 8; i++) {
        int row = row0 + ty * 8 + i;
        if (row < NN) {
            float4 v = make_float4(acc[i][0], acc[i][1], acc[i][2], acc[i][3]);
            *(float4*)&g_h2[row * HID + tx * 4] = v;
        }
    }
}

// ---------------- K9: per-node attention logits layer2 (warp per row) ----------------
__global__ void k_att2(const float* __restrict__ b1) {
    __shared__ float sb1[C1], ss[C1], sd[C1];
    int t = threadIdx.x;
    for (int i = t; i < C1; i += blockDim.x) { sb1[i] = b1[i]; ss[i] = g_w2s[i]; sd[i] = g_w2d[i]; }
    __syncthreads();
    int warp = t >> 5, lane = t & 31;
    int n = blockIdx.x * 8 + warp;
    if (n >= NN) return;
    const float* r = g_out1 + n * C1;
    float s = 0.f, d = 0.f;
    for (int k = lane; k < C1; k += 32) {
        float v = eluf(r[k] + sb1[k]);
        s += v * ss[k];
        d += v * sd[k];
    }
#pragma unroll
    for (int o = 16; o > 0; o >>= 1) {
        s += __shfl_down_sync(0xffffffffu, s, o);
        d += __shfl_down_sync(0xffffffffu, d, o);
    }
    if (lane == 0) {
        g_as2[n] = s; g_ad2[n] = d;
        float v = leaky(s + d);
        g_vs2[n] = v;
        g_m2[n] = fkey(v);
    }
}

__global__ void k_max2(const int* __restrict__ src, const int* __restrict__ dst) {
    int e = blockIdx.x * blockDim.x + threadIdx.x;
    if (e >= EE) return;
    int s = src[e], d = dst[e];
    float v = leaky(g_as2[s] + g_ad2[d]);
    g_ex2[e] = v;
    atomicMax(&g_m2[d], fkey(v));
}

__global__ void k_den2(void) {
    int n = blockIdx.x * blockDim.x + threadIdx.x;
    if (n >= NN) return;
    float exs = expf(g_vs2[n] - funkey(g_m2[n]));
    g_den2[n] = exs;
    g_vs2[n] = exs;
}

__global__ void k_exp2(const int* __restrict__ dst) {
    int e = blockIdx.x * blockDim.x + threadIdx.x;
    if (e >= EE) return;
    int d = dst[e];
    float ex = expf(g_ex2[e] - funkey(g_m2[d]));
    g_ex2[e] = ex;
    atomicAdd(&g_den2[d], ex);
}

__global__ void k_out2init(void) {
    int t = threadIdx.x;
    int n = blockIdx.x * 8 + (t >> 5);
    int lane = t & 31;
    float a = g_vs2[n] / g_den2[n];
    float4 v = *(const float4*)&g_h2[n * HID + lane * 4];
    v.x *= a; v.y *= a; v.z *= a; v.w *= a;
    *(float4*)&g_out2[n * HID + lane * 4] = v;
}

__global__ void k_scatter2(const int* __restrict__ src, const int* __restrict__ dst) {
    int t = threadIdx.x;
    int e = blockIdx.x * 8 + (t >> 5);
    if (e >= EE) return;
    int lane = t & 31;
    int s = src[e], d = dst[e];
    float a = g_ex2[e] / g_den2[d];
    float4 v = *(const float4*)&g_h2[s * HID + lane * 4];
    red_add_v4(&g_out2[d * HID + lane * 4], a * v.x, a * v.y, a * v.z, a * v.w);
}

// ---------------- K13: elu(out2+b2) + segmented mean-pool accumulation ----------------
__global__ void k_pool(const int* __restrict__ batch, const float* __restrict__ b2) {
    int c = threadIdx.x;          // 128 threads: feature dim
    int n0 = blockIdx.x * 64;
    float b2c = b2[c];
    int curg = -1;
    float acc = 0.f;
    int cnt = 0;
    for (int i = 0; i < 64; i++) {
        int n = n0 + i;
        if (n >= NN) break;
        int g = batch[n];
        if (g != curg) {
            if (curg >= 0) {
                atomicAdd(&g_pool[curg * HID + c], acc);
                if (c == 0) atomicAdd(&g_cnt[curg], (float)cnt);
            }
            curg = g; acc = 0.f; cnt = 0;
        }
        float v = g_out2[n * HID + c] + b2c;
        acc += eluf(v);
        cnt++;
    }
    if (curg >= 0) {
        atomicAdd(&g_pool[curg * HID + c], acc);
        if (c == 0) atomicAdd(&g_cnt[curg], (float)cnt);
    }
}

// ---------------- K14: graph MLP + classifier (one block per graph) ----------------
__global__ void k_final(const float* __restrict__ gfeat,
                        const float* __restrict__ Wg1, const float* __restrict__ bg1,
                        const float* __restrict__ Wg2, const float* __restrict__ bg2,
                        const float* __restrict__ Wc1, const float* __restrict__ bc1,
                        const float* __restrict__ Wc2, const float* __restrict__ bc2,
                        float* __restrict__ out) {
    int g = blockIdx.x;
    int t = threadIdx.x;   // 160 threads
    __shared__ float z[HID + 32];
    __shared__ float hg[32];
    __shared__ float gfr[10];
    __shared__ float t1[128];
    if (t < 10) gfr[t] = gfeat[g * 10 + t];
    __syncthreads();
    if (t < 32) {
        float s = bg1[t];
#pragma unroll
        for (int k = 0; k < 10; k++) s += gfr[k] * Wg1[k * 32 + t];
        hg[t] = fmaxf(s, 0.f);
    }
    if (t < HID) {
        float inv = 1.f / fmaxf(g_cnt[g], 1.f);
        z[t] = g_pool[g * HID + t] * inv;
    }
    __syncthreads();
    if (t < 32) {
        float s = bg2[t];
#pragma unroll
        for (int k = 0; k < 32; k++) s += hg[k] * Wg2[k * 32 + t];
        z[HID + t] = s;
    }
    __syncthreads();
    if (t < 128) {
        float s = bc1[t];
        for (int k = 0; k < HID + 32; k++) s += z[k] * Wc1[k * 128 + t];
        t1[t] = fmaxf(s, 0.f);
    }
    __syncthreads();
    if (t < 6) {
        float s = bc2[t];
        for (int k = 0; k < 128; k++) s += t1[k] * Wc2[k * 6 + t];
        out[g * 6 + t] = s;
    }
}

// ---------------- launch ----------------
extern "C" void kernel_launch(void* const* d_in, const int* in_sizes, int n_in,
                              void* d_out, int out_size) {
    const float* x     = (const float*)d_in[0];
    const int*   ei    = (const int*)d_in[1];
    const int*   batch = (const int*)d_in[2];
    const float* gfeat = (const float*)d_in[3];
    const float* W1    = (const float*)d_in[4];
    const float* as1   = (const float*)d_in[5];
    const float* ad1   = (const float*)d_in[6];
    const float* b1    = (const float*)d_in[7];
    const float* W2    = (const float*)d_in[8];
    const float* as2   = (const float*)d_in[9];
    const float* ad2   = (const float*)d_in[10];
    const float* b2    = (const float*)d_in[11];
    const float* Wg1   = (const float*)d_in[12];
    const float* bg1   = (const float*)d_in[13];
    const float* Wg2   = (const float*)d_in[14];
    const float* bg2   = (const float*)d_in[15];
    const float* Wc1   = (const float*)d_in[16];
    const float* bc1   = (const float*)d_in[17];
    const float* Wc2   = (const float*)d_in[18];
    const float* bc2   = (const float*)d_in[19];
    float* out = (float*)d_out;

    const int* src = ei;
    const int* dst = ei + EE;

    k_prep<<<1, 256>>>(W1, as1, ad1, W2, as2, ad2);
    k_gemm1<<<NN / 8, 512>>>(x, W1);
    k_att1<<<(NN + 255) / 256, 256>>>(x);
    k_max1<<<(EE * HEADS + 255) / 256, 256>>>(src, dst);
    k_den1<<<(NN * HEADS + 255) / 256, 256>>>();
    k_exp1<<<(EE * HEADS + 255) / 256, 256>>>(dst);
    k_out1init<<<NN / 2, 256>>>();
    k_scatter1<<<EE / 2, 256>>>(src, dst);
    k_gemm2<<<(NN + 63) / 64, 256>>>(b1, W2);
    k_att2<<<(NN + 7) / 8, 256>>>(b1);
    k_max2<<<(EE + 255) / 256, 256>>>(src, dst);
    k_den2<<<(NN + 255) / 256, 256>>>();
    k_exp2<<<(EE + 255) / 256, 256>>>(dst);
    k_out2init<<<NN / 8, 256>>>();
    k_scatter2<<<EE / 8, 256>>>(src, dst);
    k_pool<<<(NN + 63) / 64, 128>>>(batch, b2);
    k_final<<<GG, 160>>>(gfeat, Wg1, bg1, Wg2, bg2, Wc1, bc1, Wc2, bc2, out);
}

// round 2
// speedup vs baseline: 1.5696x; 1.5696x over previous
#include <cuda_runtime.h>
#include <math.h>

#define NN 50000
#define EE 400000
#define GG 64
#define FIN 16
#define HID 128
#define HEADS 4
#define C1 512   // HEADS*HID

#define SCAN_NB 196          // ceil(50000/256)
#define SCAN_PAD (SCAN_NB*256)

// ---------------- scratch (static device memory; no allocs) ----------------
__device__ float    g_h1[NN * C1];        // x@W1               102.4 MB
__device__ float    g_out1[NN * C1];      // layer1 aggregated  102.4 MB
__device__ float    g_h2[NN * HID];       // hin@W2              25.6 MB
__device__ float    g_out2[NN * HID];     // layer2 aggregated   25.6 MB
__device__ float    g_as1[NN * HEADS], g_ad1[NN * HEADS];
__device__ float    g_vs1[NN * HEADS];    // self-loop logit, then self exp
__device__ float    g_den1[NN * HEADS];
__device__ unsigned g_m1[NN * HEADS];     // monotone-key max
__device__ float    g_ex1[EE * HEADS];    // edge logit, then exp
__device__ float    g_as2[NN], g_ad2[NN], g_vs2[NN], g_den2[NN];
__device__ unsigned g_m2[NN];
__device__ float    g_ex2[EE];
__device__ float    g_Ws1[FIN * HEADS], g_Wd1[FIN * HEADS];
__device__ float    g_pool[GG * HID];
__device__ float    g_cnt[GG];
// CSR by destination
__device__ int      g_deg[SCAN_PAD];
__device__ int      g_off[SCAN_PAD + 1];
__device__ int      g_cur[NN];
__device__ int      g_part[SCAN_NB];
__device__ int      g_pref[SCAN_NB];
__device__ int      g_csr_src[EE];
__device__ int      g_csr_eid[EE];

// ---------------- helpers ----------------
__device__ __forceinline__ float leaky(float x) { return x > 0.f ? x : 0.2f * x; }
__device__ __forceinline__ float eluf(float x)  { return x > 0.f ? x : expm1f(x); }

__device__ __forceinline__ unsigned fkey(float f) {
    unsigned b = __float_as_uint(f);
    return (b & 0x80000000u) ? ~b : (b | 0x80000000u);
}
__device__ __forceinline__ float funkey(unsigned k) {
    return (k & 0x80000000u) ? __uint_as_float(k ^ 0x80000000u) : __uint_as_float(~k);
}

// ---------------- K0: fold layer1 attention vectors into W1, zero pool/deg ----------------
__global__ void k_prep(const float* __restrict__ W1, const float* __restrict__ as1,
                       const float* __restrict__ ad1) {
    int t = threadIdx.x;
    if (t < FIN * HEADS) {
        int k = t >> 2, h = t & 3;
        float s = 0.f, d = 0.f;
        for (int c = 0; c < HID; c++) {
            float w = W1[k * C1 + h * HID + c];
            s += w * as1[h * HID + c];
            d += w * ad1[h * HID + c];
        }
        g_Ws1[t] = s; g_Wd1[t] = d;
    }
    for (int i = t; i < GG * HID; i += blockDim.x) g_pool[i] = 0.f;
    if (t < GG) g_cnt[t] = 0.f;
}

__global__ void k_zero(void) {
    int i = blockIdx.x * blockDim.x + threadIdx.x;
    if (i < SCAN_PAD) g_deg[i] = 0;
}

// ---------------- CSR build ----------------
__global__ void k_hist(const int* __restrict__ dst) {
    int e = blockIdx.x * blockDim.x + threadIdx.x;
    if (e >= EE) return;
    atomicAdd(&g_deg[dst[e]], 1);
}

__global__ void k_scan_block(void) {
    __shared__ int s[256];
    int t = threadIdx.x;
    int i = blockIdx.x * 256 + t;
    int v = g_deg[i];
    s[t] = v;
    __syncthreads();
#pragma unroll
    for (int o = 1; o < 256; o <<= 1) {
        int x = (t >= o) ? s[t - o] : 0;
        __syncthreads();
        s[t] += x;
        __syncthreads();
    }
    g_off[i] = s[t] - v;          // exclusive within block
    if (t == 255) g_part[blockIdx.x] = s[255];
}

__global__ void k_scan_top(void) {
    __shared__ int s[256];
    int t = threadIdx.x;
    int v = (t < SCAN_NB) ? g_part[t] : 0;
    s[t] = v;
    __syncthreads();
#pragma unroll
    for (int o = 1; o < 256; o <<= 1) {
        int x = (t >= o) ? s[t - o] : 0;
        __syncthreads();
        s[t] += x;
        __syncthreads();
    }
    if (t < SCAN_NB) g_pref[t] = s[t] - v;
}

__global__ void k_scan_add(void) {
    int i = blockIdx.x * blockDim.x + threadIdx.x;
    if (i > SCAN_PAD) return;
    int p = (i < SCAN_PAD) ? (g_off[i] + g_pref[i >> 8]) : EE;
    if (i == SCAN_PAD) g_off[i] = EE;
    else g_off[i] = p;
    if (i < NN) g_cur[i] = p;
}

__global__ void k_fill(const int* __restrict__ src, const int* __restrict__ dst) {
    int e = blockIdx.x * blockDim.x + threadIdx.x;
    if (e >= EE) return;
    int d = dst[e];
    int p = atomicAdd(&g_cur[d], 1);
    g_csr_src[p] = src[e];
    g_csr_eid[p] = e;
}

// ---------------- K1: h1 = x @ W1 ----------------
__global__ void k_gemm1(const float* __restrict__ x, const float* __restrict__ W1) {
    __shared__ float sx[8][FIN];
    int t = threadIdx.x;
    int row0 = blockIdx.x * 8;
    if (t < 8 * FIN) {
        int r = t >> 4, k = t & 15;
        sx[r][k] = x[(row0 + r) * FIN + k];
    }
    __syncthreads();
    float w[FIN];
#pragma unroll
    for (int k = 0; k < FIN; k++) w[k] = W1[k * C1 + t];
#pragma unroll
    for (int r = 0; r < 8; r++) {
        float a = 0.f;
#pragma unroll
        for (int k = 0; k < FIN; k++) a += sx[r][k] * w[k];
        g_h1[(row0 + r) * C1 + t] = a;
    }
}

// ---------------- K2: per-node attention logits layer1 + init max ----------------
__global__ void k_att1(const float* __restrict__ x) {
    __shared__ float ws[FIN * HEADS], wd[FIN * HEADS];
    int t = threadIdx.x;
    if (t < FIN * HEADS) { ws[t] = g_Ws1[t]; wd[t] = g_Wd1[t]; }
    __syncthreads();
    int n = blockIdx.x * blockDim.x + t;
    if (n >= NN) return;
    float xr[FIN];
    const float4* xp = (const float4*)(x + n * FIN);
#pragma unroll
    for (int i = 0; i < 4; i++) {
        float4 v = xp[i];
        xr[i * 4 + 0] = v.x; xr[i * 4 + 1] = v.y; xr[i * 4 + 2] = v.z; xr[i * 4 + 3] = v.w;
    }
#pragma unroll
    for (int h = 0; h < HEADS; h++) {
        float s = 0.f, d = 0.f;
#pragma unroll
        for (int k = 0; k < FIN; k++) { s += xr[k] * ws[k * 4 + h]; d += xr[k] * wd[k * 4 + h]; }
        g_as1[n * 4 + h] = s;
        g_ad1[n * 4 + h] = d;
        float v = leaky(s + d);
        g_vs1[n * 4 + h] = v;
        g_m1[n * 4 + h] = fkey(v);
    }
}

// ---------------- K3: edge max pass (layer1) ----------------
__global__ void k_max1(const int* __restrict__ src, const int* __restrict__ dst) {
    int i = blockIdx.x * blockDim.x + threadIdx.x;
    if (i >= EE * HEADS) return;
    int e = i >> 2, h = i & 3;
    int s = src[e], d = dst[e];
    float v = leaky(g_as1[s * 4 + h] + g_ad1[d * 4 + h]);
    g_ex1[i] = v;
    atomicMax(&g_m1[d * 4 + h], fkey(v));
}

__global__ void k_den1(void) {
    int i = blockIdx.x * blockDim.x + threadIdx.x;
    if (i >= NN * HEADS) return;
    float m = funkey(g_m1[i]);
    float exs = expf(g_vs1[i] - m);
    g_den1[i] = exs;
    g_vs1[i] = exs;
}

__global__ void k_exp1(const int* __restrict__ dst) {
    int i = blockIdx.x * blockDim.x + threadIdx.x;
    if (i >= EE * HEADS) return;
    int e = i >> 2, h = i & 3;
    int d = dst[e];
    float ex = expf(g_ex1[i] - funkey(g_m1[d * 4 + h]));
    g_ex1[i] = ex;
    atomicAdd(&g_den1[d * 4 + h], ex);
}

// ---------------- K7: layer1 gather-aggregate (CSR, one block=128 thr per node) -------
__global__ void k_agg1(void) {
    int n = blockIdx.x;
    int c4 = threadIdx.x;      // 0..127 -> cols c4*4..c4*4+3
    int h = c4 >> 5;
    float dinv = 1.f / g_den1[n * 4 + h];
    float a = g_vs1[n * 4 + h] * dinv;   // self-loop alpha
    float4 v = *(const float4*)&g_h1[n * C1 + c4 * 4];
    float4 acc = make_float4(a * v.x, a * v.y, a * v.z, a * v.w);
    int p = g_off[n], pe = g_off[n + 1];
    for (; p + 1 < pe; p += 2) {
        int s0 = g_csr_src[p],     e0 = g_csr_eid[p];
        int s1 = g_csr_src[p + 1], e1 = g_csr_eid[p + 1];
        float a0 = g_ex1[e0 * 4 + h] * dinv;
        float a1 = g_ex1[e1 * 4 + h] * dinv;
        float4 v0 = *(const float4*)&g_h1[s0 * C1 + c4 * 4];
        float4 v1 = *(const float4*)&g_h1[s1 * C1 + c4 * 4];
        acc.x += a0 * v0.x + a1 * v1.x;
        acc.y += a0 * v0.y + a1 * v1.y;
        acc.z += a0 * v0.z + a1 * v1.z;
        acc.w += a0 * v0.w + a1 * v1.w;
    }
    if (p < pe) {
        int s0 = g_csr_src[p], e0 = g_csr_eid[p];
        float a0 = g_ex1[e0 * 4 + h] * dinv;
        float4 v0 = *(const float4*)&g_h1[s0 * C1 + c4 * 4];
        acc.x += a0 * v0.x; acc.y += a0 * v0.y; acc.z += a0 * v0.z; acc.w += a0 * v0.w;
    }
    *(float4*)&g_out1[n * C1 + c4 * 4] = acc;
}

// ---------------- K8: h2 = elu(out1+b1) @ W2, fused layer2 attention logits ----------------
__global__ void k_gemm2(const float* __restrict__ b1, const float* __restrict__ W2,
                        const float* __restrict__ as2, const float* __restrict__ ad2) {
    __shared__ float As[16 * 65];
    __shared__ float Bs[16 * 128];
    __shared__ float sa[HID], sd[HID];
    int t = threadIdx.x;
    int tx = t & 31;
    int ty = t >> 5;
    int row0 = blockIdx.x * 64;
    if (t < HID) { sa[t] = as2[t]; sd[t] = ad2[t]; }
    float acc[8][4];
#pragma unroll
    for (int i = 0; i < 8; i++)
#pragma unroll
        for (int j = 0; j < 4; j++) acc[i][j] = 0.f;

    for (int kt = 0; kt < C1; kt += 16) {
#pragma unroll
        for (int l = 0; l < 4; l++) {
            int idx = t + l * 256;
            int m = idx >> 4, k = idx & 15;
            int row = row0 + m;
            float v = 0.f;
            if (row < NN) {
                v = g_out1[row * C1 + kt + k] + b1[kt + k];
                v = eluf(v);
            }
            As[k * 65 + m] = v;
        }
#pragma unroll
        for (int l = 0; l < 8; l++) {
            int idx = t + l * 256;
            int k = idx >> 7, c = idx & 127;
            Bs[k * 128 + c] = W2[(kt + k) * HID + c];
        }
        __syncthreads();
#pragma unroll
        for (int k = 0; k < 16; k++) {
            float4 bv = *(const float4*)&Bs[k * 128 + tx * 4];
#pragma unroll
            for (int i = 0; i < 8; i++) {
                float av = As[k * 65 + ty * 8 + i];
                acc[i][0] += av * bv.x;
                acc[i][1] += av * bv.y;
                acc[i][2] += av * bv.z;
                acc[i][3] += av * bv.w;
            }
        }
        __syncthreads();
    }
    float4 av = *(const float4*)&sa[tx * 4];
    float4 dv = *(const float4*)&sd[tx * 4];
#pragma unroll
    for (int i = 0; i < 8; i++) {
        int row = row0 + ty * 8 + i;
        if (row < NN) {
            float4 v = make_float4(acc[i][0], acc[i][1], acc[i][2], acc[i][3]);
            *(float4*)&g_h2[row * HID + tx * 4] = v;
        }
        // fused attention logits: warp owns this row fully
        float s = acc[i][0] * av.x + acc[i][1] * av.y + acc[i][2] * av.z + acc[i][3] * av.w;
        float d = acc[i][0] * dv.x + acc[i][1] * dv.y + acc[i][2] * dv.z + acc[i][3] * dv.w;
#pragma unroll
        for (int o = 16; o > 0; o >>= 1) {
            s += __shfl_xor_sync(0xffffffffu, s, o);
            d += __shfl_xor_sync(0xffffffffu, d, o);
        }
        if (tx == 0 && row < NN) {
            g_as2[row] = s; g_ad2[row] = d;
            float v = leaky(s + d);
            g_vs2[row] = v;
            g_m2[row] = fkey(v);
        }
    }
}

__global__ void k_max2(const int* __restrict__ src, const int* __restrict__ dst) {
    int e = blockIdx.x * blockDim.x + threadIdx.x;
    if (e >= EE) return;
    int s = src[e], d = dst[e];
    float v = leaky(g_as2[s] + g_ad2[d]);
    g_ex2[e] = v;
    atomicMax(&g_m2[d], fkey(v));
}

__global__ void k_den2(void) {
    int n = blockIdx.x * blockDim.x + threadIdx.x;
    if (n >= NN) return;
    float exs = expf(g_vs2[n] - funkey(g_m2[n]));
    g_den2[n] = exs;
    g_vs2[n] = exs;
}

__global__ void k_exp2(const int* __restrict__ dst) {
    int e = blockIdx.x * blockDim.x + threadIdx.x;
    if (e >= EE) return;
    int d = dst[e];
    float ex = expf(g_ex2[e] - funkey(g_m2[d]));
    g_ex2[e] = ex;
    atomicAdd(&g_den2[d], ex);
}

// ---------------- K12: layer2 gather-aggregate (4 nodes/block, 32 thr/node) -------
__global__ void k_agg2(void) {
    int t = threadIdx.x;
    int n = blockIdx.x * 4 + (t >> 5);
    if (n >= NN) return;
    int lane = t & 31;
    float dinv = 1.f / g_den2[n];
    float a = g_vs2[n] * dinv;
    float4 v = *(const float4*)&g_h2[n * HID + lane * 4];
    float4 acc = make_float4(a * v.x, a * v.y, a * v.z, a * v.w);
    int p = g_off[n], pe = g_off[n + 1];
    for (; p + 1 < pe; p += 2) {
        int s0 = g_csr_src[p],     e0 = g_csr_eid[p];
        int s1 = g_csr_src[p + 1], e1 = g_csr_eid[p + 1];
        float a0 = g_ex2[e0] * dinv;
        float a1 = g_ex2[e1] * dinv;
        float4 v0 = *(const float4*)&g_h2[s0 * HID + lane * 4];
        float4 v1 = *(const float4*)&g_h2[s1 * HID + lane * 4];
        acc.x += a0 * v0.x + a1 * v1.x;
        acc.y += a0 * v0.y + a1 * v1.y;
        acc.z += a0 * v0.z + a1 * v1.z;
        acc.w += a0 * v0.w + a1 * v1.w;
    }
    if (p < pe) {
        int s0 = g_csr_src[p], e0 = g_csr_eid[p];
        float a0 = g_ex2[e0] * dinv;
        float4 v0 = *(const float4*)&g_h2[s0 * HID + lane * 4];
        acc.x += a0 * v0.x; acc.y += a0 * v0.y; acc.z += a0 * v0.z; acc.w += a0 * v0.w;
    }
    *(float4*)&g_out2[n * HID + lane * 4] = acc;
}

// ---------------- K13: elu(out2+b2) + segmented mean-pool accumulation ----------------
__global__ void k_pool(const int* __restrict__ batch, const float* __restrict__ b2) {
    int c = threadIdx.x;
    int n0 = blockIdx.x * 64;
    float b2c = b2[c];
    int curg = -1;
    float acc = 0.f;
    int cnt = 0;
    for (int i = 0; i < 64; i++) {
        int n = n0 + i;
        if (n >= NN) break;
        int g = batch[n];
        if (g != curg) {
            if (curg >= 0) {
                atomicAdd(&g_pool[curg * HID + c], acc);
                if (c == 0) atomicAdd(&g_cnt[curg], (float)cnt);
            }
            curg = g; acc = 0.f; cnt = 0;
        }
        float v = g_out2[n * HID + c] + b2c;
        acc += eluf(v);
        cnt++;
    }
    if (curg >= 0) {
        atomicAdd(&g_pool[curg * HID + c], acc);
        if (c == 0) atomicAdd(&g_cnt[curg], (float)cnt);
    }
}

// ---------------- K14: graph MLP + classifier ----------------
__global__ void k_final(const float* __restrict__ gfeat,
                        const float* __restrict__ Wg1, const float* __restrict__ bg1,
                        const float* __restrict__ Wg2, const float* __restrict__ bg2,
                        const float* __restrict__ Wc1, const float* __restrict__ bc1,
                        const float* __restrict__ Wc2, const float* __restrict__ bc2,
                        float* __restrict__ out) {
    int g = blockIdx.x;
    int t = threadIdx.x;
    __shared__ float z[HID + 32];
    __shared__ float hg[32];
    __shared__ float gfr[10];
    __shared__ float t1[128];
    if (t < 10) gfr[t] = gfeat[g * 10 + t];
    __syncthreads();
    if (t < 32) {
        float s = bg1[t];
#pragma unroll
        for (int k = 0; k < 10; k++) s += gfr[k] * Wg1[k * 32 + t];
        hg[t] = fmaxf(s, 0.f);
    }
    if (t < HID) {
        float inv = 1.f / fmaxf(g_cnt[g], 1.f);
        z[t] = g_pool[g * HID + t] * inv;
    }
    __syncthreads();
    if (t < 32) {
        float s = bg2[t];
#pragma unroll
        for (int k = 0; k < 32; k++) s += hg[k] * Wg2[k * 32 + t];
        z[HID + t] = s;
    }
    __syncthreads();
    if (t < 128) {
        float s = bc1[t];
        for (int k = 0; k < HID + 32; k++) s += z[k] * Wc1[k * 128 + t];
        t1[t] = fmaxf(s, 0.f);
    }
    __syncthreads();
    if (t < 6) {
        float s = bc2[t];
        for (int k = 0; k < 128; k++) s += t1[k] * Wc2[k * 6 + t];
        out[g * 6 + t] = s;
    }
}

// ---------------- launch ----------------
extern "C" void kernel_launch(void* const* d_in, const int* in_sizes, int n_in,
                              void* d_out, int out_size) {
    const float* x     = (const float*)d_in[0];
    const int*   ei    = (const int*)d_in[1];
    const int*   batch = (const int*)d_in[2];
    const float* gfeat = (const float*)d_in[3];
    const float* W1    = (const float*)d_in[4];
    const float* as1   = (const float*)d_in[5];
    const float* ad1   = (const float*)d_in[6];
    const float* b1    = (const float*)d_in[7];
    const float* W2    = (const float*)d_in[8];
    const float* as2   = (const float*)d_in[9];
    const float* ad2   = (const float*)d_in[10];
    const float* b2    = (const float*)d_in[11];
    const float* Wg1   = (const float*)d_in[12];
    const float* bg1   = (const float*)d_in[13];
    const float* Wg2   = (const float*)d_in[14];
    const float* bg2   = (const float*)d_in[15];
    const float* Wc1   = (const float*)d_in[16];
    const float* bc1   = (const float*)d_in[17];
    const float* Wc2   = (const float*)d_in[18];
    const float* bc2   = (const float*)d_in[19];
    float* out = (float*)d_out;

    const int* src = ei;
    const int* dst = ei + EE;

    k_prep<<<1, 256>>>(W1, as1, ad1);
    k_zero<<<(SCAN_PAD + 255) / 256, 256>>>();
    k_gemm1<<<NN / 8, 512>>>(x, W1);
    k_att1<<<(NN + 255) / 256, 256>>>(x);
    // CSR build
    k_hist<<<(EE + 255) / 256, 256>>>(dst);
    k_scan_block<<<SCAN_NB, 256>>>();
    k_scan_top<<<1, 256>>>();
    k_scan_add<<<(SCAN_PAD + 256) / 256, 256>>>();
    k_fill<<<(EE + 255) / 256, 256>>>(src, dst);
    // layer1 softmax
    k_max1<<<(EE * HEADS + 255) / 256, 256>>>(src, dst);
    k_den1<<<(NN * HEADS + 255) / 256, 256>>>();
    k_exp1<<<(EE * HEADS + 255) / 256, 256>>>(dst);
    // layer1 aggregate (gather)
    k_agg1<<<NN, 128>>>();
    // layer2
    k_gemm2<<<(NN + 63) / 64, 256>>>(b1, W2, as2, ad2);
    k_max2<<<(EE + 255) / 256, 256>>>(src, dst);
    k_den2<<<(NN + 255) / 256, 256>>>();
    k_exp2<<<(EE + 255) / 256, 256>>>(dst);
    k_agg2<<<(NN + 3) / 4, 128>>>();
    // pool + heads
    k_pool<<<(NN + 63) / 64, 128>>>(batch, b2);
    k_final<<<GG, 160>>>(gfeat, Wg1, bg1, Wg2, bg2, Wc1, bc1, Wc2, bc2, out);
}

// round 3
// speedup vs baseline: 1.8581x; 1.1838x over previous
#include <cuda_runtime.h>
#include <cuda_fp16.h>
#include <math.h>

#define NN 50000
#define EE 400000
#define GG 64
#define FIN 16
#define HID 128
#define HEADS 4
#define C1 512   // HEADS*HID
#define MAXD 64

#define SCAN_NB 196          // ceil(50000/256)
#define SCAN_PAD (SCAN_NB*256)

// ---------------- scratch (static device memory; no allocs) ----------------
__device__ __half   g_h1h[NN * C1];       // x@W1 (fp16)         51.2 MB
__device__ __half   g_out1h[NN * C1];     // layer1 agg (fp16)   51.2 MB
__device__ __half   g_h2h[NN * HID];      // fp16                12.8 MB
__device__ __half   g_out2h[NN * HID];    // fp16                12.8 MB
__device__ float    g_as1[NN * HEADS], g_ad1[NN * HEADS];
__device__ float    g_as2[NN], g_ad2[NN];
__device__ float    g_Ws1[FIN * HEADS], g_Wd1[FIN * HEADS];
__device__ float    g_pool[GG * HID];
__device__ float    g_cnt[GG];
// CSR by destination
__device__ int      g_deg[SCAN_PAD];
__device__ int      g_off[SCAN_PAD + 1];
__device__ int      g_cur[NN];
__device__ int      g_part[SCAN_NB];
__device__ int      g_pref[SCAN_NB];
__device__ int      g_csr_src[EE];

// ---------------- helpers ----------------
__device__ __forceinline__ float leaky(float x) { return x > 0.f ? x : 0.2f * x; }
__device__ __forceinline__ float eluf(float x)  { return x > 0.f ? x : expm1f(x); }

__device__ __forceinline__ float4 h4_to_f4(uint2 u) {
    __half2 a = *(__half2*)&u.x, b = *(__half2*)&u.y;
    float2 fa = __half22float2(a), fb = __half22float2(b);
    return make_float4(fa.x, fa.y, fb.x, fb.y);
}
__device__ __forceinline__ uint2 f4_to_h4(float4 v) {
    __half2 a = __floats2half2_rn(v.x, v.y), b = __floats2half2_rn(v.z, v.w);
    uint2 u; u.x = *(unsigned*)&a; u.y = *(unsigned*)&b; return u;
}

// ---------------- K0: fold layer1 attention vectors into W1, zero pool ----------------
__global__ void k_prep(const float* __restrict__ W1, const float* __restrict__ as1,
                       const float* __restrict__ ad1) {
    int t = threadIdx.x;
    if (t < FIN * HEADS) {
        int k = t >> 2, h = t & 3;
        float s = 0.f, d = 0.f;
        for (int c = 0; c < HID; c++) {
            float w = W1[k * C1 + h * HID + c];
            s += w * as1[h * HID + c];
            d += w * ad1[h * HID + c];
        }
        g_Ws1[t] = s; g_Wd1[t] = d;
    }
    for (int i = t; i < GG * HID; i += blockDim.x) g_pool[i] = 0.f;
    if (t < GG) g_cnt[t] = 0.f;
}

__global__ void k_zero(void) {
    int i = blockIdx.x * blockDim.x + threadIdx.x;
    if (i < SCAN_PAD) g_deg[i] = 0;
}

// ---------------- CSR build ----------------
__global__ void k_hist(const int* __restrict__ dst) {
    int e = blockIdx.x * blockDim.x + threadIdx.x;
    if (e >= EE) return;
    atomicAdd(&g_deg[dst[e]], 1);
}

__global__ void k_scan_block(void) {
    __shared__ int s[256];
    int t = threadIdx.x;
    int i = blockIdx.x * 256 + t;
    int v = g_deg[i];
    s[t] = v;
    __syncthreads();
#pragma unroll
    for (int o = 1; o < 256; o <<= 1) {
        int x = (t >= o) ? s[t - o] : 0;
        __syncthreads();
        s[t] += x;
        __syncthreads();
    }
    g_off[i] = s[t] - v;
    if (t == 255) g_part[blockIdx.x] = s[255];
}

__global__ void k_scan_top(void) {
    __shared__ int s[256];
    int t = threadIdx.x;
    int v = (t < SCAN_NB) ? g_part[t] : 0;
    s[t] = v;
    __syncthreads();
#pragma unroll
    for (int o = 1; o < 256; o <<= 1) {
        int x = (t >= o) ? s[t - o] : 0;
        __syncthreads();
        s[t] += x;
        __syncthreads();
    }
    if (t < SCAN_NB) g_pref[t] = s[t] - v;
}

__global__ void k_scan_add(void) {
    int i = blockIdx.x * blockDim.x + threadIdx.x;
    if (i > SCAN_PAD) return;
    if (i == SCAN_PAD) { g_off[i] = EE; return; }
    int p = g_off[i] + g_pref[i >> 8];
    g_off[i] = p;
    if (i < NN) g_cur[i] = p;
}

__global__ void k_fill(const int* __restrict__ src, const int* __restrict__ dst) {
    int e = blockIdx.x * blockDim.x + threadIdx.x;
    if (e >= EE) return;
    int d = dst[e];
    int p = atomicAdd(&g_cur[d], 1);
    g_csr_src[p] = src[e];
}

// ---------------- K1: h1 = x @ W1 (fp16 out) ----------------
__global__ void k_gemm1(const float* __restrict__ x, const float* __restrict__ W1) {
    __shared__ float sx[8][FIN];
    int t = threadIdx.x;
    int row0 = blockIdx.x * 8;
    if (t < 8 * FIN) {
        int r = t >> 4, k = t & 15;
        sx[r][k] = x[(row0 + r) * FIN + k];
    }
    __syncthreads();
    float w[FIN];
#pragma unroll
    for (int k = 0; k < FIN; k++) w[k] = W1[k * C1 + t];
#pragma unroll
    for (int r = 0; r < 8; r++) {
        float a = 0.f;
#pragma unroll
        for (int k = 0; k < FIN; k++) a += sx[r][k] * w[k];
        g_h1h[(row0 + r) * C1 + t] = __float2half_rn(a);
    }
}

// ---------------- K2: per-node attention logits layer1 ----------------
__global__ void k_att1(const float* __restrict__ x) {
    __shared__ float ws[FIN * HEADS], wd[FIN * HEADS];
    int t = threadIdx.x;
    if (t < FIN * HEADS) { ws[t] = g_Ws1[t]; wd[t] = g_Wd1[t]; }
    __syncthreads();
    int n = blockIdx.x * blockDim.x + t;
    if (n >= NN) return;
    float xr[FIN];
    const float4* xp = (const float4*)(x + n * FIN);
#pragma unroll
    for (int i = 0; i < 4; i++) {
        float4 v = xp[i];
        xr[i * 4 + 0] = v.x; xr[i * 4 + 1] = v.y; xr[i * 4 + 2] = v.z; xr[i * 4 + 3] = v.w;
    }
#pragma unroll
    for (int h = 0; h < HEADS; h++) {
        float s = 0.f, d = 0.f;
#pragma unroll
        for (int k = 0; k < FIN; k++) { s += xr[k] * ws[k * 4 + h]; d += xr[k] * wd[k * 4 + h]; }
        g_as1[n * 4 + h] = s;
        g_ad1[n * 4 + h] = d;
    }
}

// ---------------- K3: layer1 fused softmax + gather (block=128 thr per node) -------
__global__ void k_agg1(void) {
    __shared__ int   ssrc[MAXD];
    __shared__ float salpha[MAXD * 4];
    __shared__ float sM[4], sSinv[4], sAself[4];
    int n = blockIdx.x;
    int t = threadIdx.x;
    int w = t >> 5, lane = t & 31;
    int p0 = g_off[n], deg = g_off[n + 1] - p0;
    int degc = min(deg, MAXD);
    for (int i = t; i < degc; i += 128) ssrc[i] = g_csr_src[p0 + i];
    __syncthreads();
    // stats: warp w handles head w (online softmax)
    {
        float adn = g_ad1[n * 4 + w];
        float vself = leaky(g_as1[n * 4 + w] + adn);
        float M = (lane == 0) ? vself : -1e30f;
        float S = (lane == 0) ? 1.f : 0.f;
        for (int i = lane; i < deg; i += 32) {
            int s = (i < MAXD) ? ssrc[i] : g_csr_src[p0 + i];
            float v = leaky(g_as1[s * 4 + w] + adn);
            float Mn = fmaxf(M, v);
            S = S * __expf(M - Mn) + __expf(v - Mn);
            M = Mn;
        }
#pragma unroll
        for (int o = 16; o > 0; o >>= 1) {
            float Mo = __shfl_xor_sync(0xffffffffu, M, o);
            float So = __shfl_xor_sync(0xffffffffu, S, o);
            float Mn = fmaxf(M, Mo);
            S = S * __expf(M - Mn) + So * __expf(Mo - Mn);
            M = Mn;
        }
        if (lane == 0) {
            float si = 1.f / S;
            sM[w] = M; sSinv[w] = si;
            sAself[w] = __expf(vself - M) * si;
        }
    }
    __syncthreads();
    // alpha table
    for (int i = t; i < degc * 4; i += 128) {
        int e = i >> 2, h = i & 3;
        int s = ssrc[e];
        float v = leaky(g_as1[s * 4 + h] + g_ad1[n * 4 + h]);
        salpha[i] = __expf(v - sM[h]) * sSinv[h];
    }
    __syncthreads();
    // gather: thread t owns 4 halves (uint2) of the 512-wide row
    int h = t >> 5;
    const uint2* h1p = (const uint2*)g_h1h;
    float Mh = sM[h], Sinvh = sSinv[h], adnh = g_ad1[n * 4 + h];
    float4 acc;
    {
        float a = sAself[h];
        float4 v = h4_to_f4(h1p[n * 128 + t]);
        acc = make_float4(a * v.x, a * v.y, a * v.z, a * v.w);
    }
    int e = 0;
    for (; e + 1 < degc; e += 2) {
        int s0 = ssrc[e], s1 = ssrc[e + 1];
        float a0 = salpha[e * 4 + h], a1 = salpha[(e + 1) * 4 + h];
        float4 v0 = h4_to_f4(h1p[s0 * 128 + t]);
        float4 v1 = h4_to_f4(h1p[s1 * 128 + t]);
        acc.x += a0 * v0.x + a1 * v1.x;
        acc.y += a0 * v0.y + a1 * v1.y;
        acc.z += a0 * v0.z + a1 * v1.z;
        acc.w += a0 * v0.w + a1 * v1.w;
    }
    for (; e < deg; e++) {
        int s; float a;
        if (e < MAXD) { s = ssrc[e]; a = salpha[e * 4 + h]; }
        else {
            s = g_csr_src[p0 + e];
            a = __expf(leaky(g_as1[s * 4 + h] + adnh) - Mh) * Sinvh;
        }
        float4 v = h4_to_f4(h1p[s * 128 + t]);
        acc.x += a * v.x; acc.y += a * v.y; acc.z += a * v.z; acc.w += a * v.w;
    }
    ((uint2*)g_out1h)[n * 128 + t] = f4_to_h4(acc);
}

// ---------------- K8: h2 = elu(out1+b1) @ W2, fused layer2 attention logits ----------------
__global__ void k_gemm2(const float* __restrict__ b1, const float* __restrict__ W2,
                        const float* __restrict__ as2, const float* __restrict__ ad2) {
    __shared__ float As[16 * 65];
    __shared__ float Bs[16 * 128];
    __shared__ float sa[HID], sd[HID];
    int t = threadIdx.x;
    int tx = t & 31;
    int ty = t >> 5;
    int row0 = blockIdx.x * 64;
    if (t < HID) { sa[t] = as2[t]; sd[t] = ad2[t]; }
    float acc[8][4];
#pragma unroll
    for (int i = 0; i < 8; i++)
#pragma unroll
        for (int j = 0; j < 4; j++) acc[i][j] = 0.f;

    for (int kt = 0; kt < C1; kt += 16) {
#pragma unroll
        for (int l = 0; l < 4; l++) {
            int idx = t + l * 256;
            int m = idx >> 4, k = idx & 15;
            int row = row0 + m;
            float v = 0.f;
            if (row < NN) {
                v = __half2float(g_out1h[row * C1 + kt + k]) + b1[kt + k];
                v = eluf(v);
            }
            As[k * 65 + m] = v;
        }
#pragma unroll
        for (int l = 0; l < 8; l++) {
            int idx = t + l * 256;
            int k = idx >> 7, c = idx & 127;
            Bs[k * 128 + c] = W2[(kt + k) * HID + c];
        }
        __syncthreads();
#pragma unroll
        for (int k = 0; k < 16; k++) {
            float4 bv = *(const float4*)&Bs[k * 128 + tx * 4];
#pragma unroll
            for (int i = 0; i < 8; i++) {
                float av = As[k * 65 + ty * 8 + i];
                acc[i][0] += av * bv.x;
                acc[i][1] += av * bv.y;
                acc[i][2] += av * bv.z;
                acc[i][3] += av * bv.w;
            }
        }
        __syncthreads();
    }
    float4 av = *(const float4*)&sa[tx * 4];
    float4 dv = *(const float4*)&sd[tx * 4];
#pragma unroll
    for (int i = 0; i < 8; i++) {
        int row = row0 + ty * 8 + i;
        if (row < NN) {
            float4 v = make_float4(acc[i][0], acc[i][1], acc[i][2], acc[i][3]);
            ((uint2*)g_h2h)[row * 32 + tx] = f4_to_h4(v);
        }
        float s = acc[i][0] * av.x + acc[i][1] * av.y + acc[i][2] * av.z + acc[i][3] * av.w;
        float d = acc[i][0] * dv.x + acc[i][1] * dv.y + acc[i][2] * dv.z + acc[i][3] * dv.w;
#pragma unroll
        for (int o = 16; o > 0; o >>= 1) {
            s += __shfl_xor_sync(0xffffffffu, s, o);
            d += __shfl_xor_sync(0xffffffffu, d, o);
        }
        if (tx == 0 && row < NN) {
            g_as2[row] = s; g_ad2[row] = d;
        }
    }
}

// ---------------- K12: layer2 fused softmax + gather (warp per node, 4/block) -------
__global__ void k_agg2(void) {
    __shared__ int   ssrc[4][MAXD];
    __shared__ float salpha[4][MAXD];
    int t = threadIdx.x;
    int w = t >> 5, lane = t & 31;
    int n = blockIdx.x * 4 + w;          // NN divisible by 4
    int p0 = g_off[n], deg = g_off[n + 1] - p0;
    int degc = min(deg, MAXD);
    for (int i = lane; i < degc; i += 32) ssrc[w][i] = g_csr_src[p0 + i];
    __syncwarp();
    float adn = g_ad2[n];
    float vself = leaky(g_as2[n] + adn);
    float M = (lane == 0) ? vself : -1e30f;
    float S = (lane == 0) ? 1.f : 0.f;
    for (int i = lane; i < deg; i += 32) {
        int s = (i < MAXD) ? ssrc[w][i] : g_csr_src[p0 + i];
        float v = leaky(g_as2[s] + adn);
        float Mn = fmaxf(M, v);
        S = S * __expf(M - Mn) + __expf(v - Mn);
        M = Mn;
    }
#pragma unroll
    for (int o = 16; o > 0; o >>= 1) {
        float Mo = __shfl_xor_sync(0xffffffffu, M, o);
        float So = __shfl_xor_sync(0xffffffffu, S, o);
        float Mn = fmaxf(M, Mo);
        S = S * __expf(M - Mn) + So * __expf(Mo - Mn);
        M = Mn;
    }
    float Sinv = 1.f / S;
    float aself = __expf(vself - M) * Sinv;
    for (int i = lane; i < degc; i += 32) {
        int s = ssrc[w][i];
        salpha[w][i] = __expf(leaky(g_as2[s] + adn) - M) * Sinv;
    }
    __syncwarp();
    const uint2* h2p = (const uint2*)g_h2h;   // row = 32 uint2
    float4 acc;
    {
        float4 v = h4_to_f4(h2p[n * 32 + lane]);
        acc = make_float4(aself * v.x, aself * v.y, aself * v.z, aself * v.w);
    }
    int e = 0;
    for (; e + 1 < degc; e += 2) {
        int s0 = ssrc[w][e], s1 = ssrc[w][e + 1];
        float a0 = salpha[w][e], a1 = salpha[w][e + 1];
        float4 v0 = h4_to_f4(h2p[s0 * 32 + lane]);
        float4 v1 = h4_to_f4(h2p[s1 * 32 + lane]);
        acc.x += a0 * v0.x + a1 * v1.x;
        acc.y += a0 * v0.y + a1 * v1.y;
        acc.z += a0 * v0.z + a1 * v1.z;
        acc.w += a0 * v0.w + a1 * v1.w;
    }
    for (; e < deg; e++) {
        int s; float a;
        if (e < MAXD) { s = ssrc[w][e]; a = salpha[w][e]; }
        else {
            s = g_csr_src[p0 + e];
            a = __expf(leaky(g_as2[s] + adn) - M) * Sinv;
        }
        float4 v = h4_to_f4(h2p[s * 32 + lane]);
        acc.x += a * v.x; acc.y += a * v.y; acc.z += a * v.z; acc.w += a * v.w;
    }
    ((uint2*)g_out2h)[n * 32 + lane] = f4_to_h4(acc);
}

// ---------------- K13: elu(out2+b2) + segmented mean-pool ----------------
__global__ void k_pool(const int* __restrict__ batch, const float* __restrict__ b2) {
    int c = threadIdx.x;
    int n0 = blockIdx.x * 64;
    float b2c = b2[c];
    int curg = -1;
    float acc = 0.f;
    int cnt = 0;
    for (int i = 0; i < 64; i++) {
        int n = n0 + i;
        if (n >= NN) break;
        int g = batch[n];
        if (g != curg) {
            if (curg >= 0) {
                atomicAdd(&g_pool[curg * HID + c], acc);
                if (c == 0) atomicAdd(&g_cnt[curg], (float)cnt);
            }
            curg = g; acc = 0.f; cnt = 0;
        }
        float v = __half2float(g_out2h[n * HID + c]) + b2c;
        acc += eluf(v);
        cnt++;
    }
    if (curg >= 0) {
        atomicAdd(&g_pool[curg * HID + c], acc);
        if (c == 0) atomicAdd(&g_cnt[curg], (float)cnt);
    }
}

// ---------------- K14: graph MLP + classifier ----------------
__global__ void k_final(const float* __restrict__ gfeat,
                        const float* __restrict__ Wg1, const float* __restrict__ bg1,
                        const float* __restrict__ Wg2, const float* __restrict__ bg2,
                        const float* __restrict__ Wc1, const float* __restrict__ bc1,
                        const float* __restrict__ Wc2, const float* __restrict__ bc2,
                        float* __restrict__ out) {
    int g = blockIdx.x;
    int t = threadIdx.x;
    __shared__ float z[HID + 32];
    __shared__ float hg[32];
    __shared__ float gfr[10];
    __shared__ float t1[128];
    if (t < 10) gfr[t] = gfeat[g * 10 + t];
    __syncthreads();
    if (t < 32) {
        float s = bg1[t];
#pragma unroll
        for (int k = 0; k < 10; k++) s += gfr[k] * Wg1[k * 32 + t];
        hg[t] = fmaxf(s, 0.f);
    }
    if (t < HID) {
        float inv = 1.f / fmaxf(g_cnt[g], 1.f);
        z[t] = g_pool[g * HID + t] * inv;
    }
    __syncthreads();
    if (t < 32) {
        float s = bg2[t];
#pragma unroll
        for (int k = 0; k < 32; k++) s += hg[k] * Wg2[k * 32 + t];
        z[HID + t] = s;
    }
    __syncthreads();
    if (t < 128) {
        float s = bc1[t];
        for (int k = 0; k < HID + 32; k++) s += z[k] * Wc1[k * 128 + t];
        t1[t] = fmaxf(s, 0.f);
    }
    __syncthreads();
    if (t < 6) {
        float s = bc2[t];
        for (int k = 0; k < 128; k++) s += t1[k] * Wc2[k * 6 + t];
        out[g * 6 + t] = s;
    }
}

// ---------------- launch ----------------
extern "C" void kernel_launch(void* const* d_in, const int* in_sizes, int n_in,
                              void* d_out, int out_size) {
    const float* x     = (const float*)d_in[0];
    const int*   ei    = (const int*)d_in[1];
    const int*   batch = (const int*)d_in[2];
    const float* gfeat = (const float*)d_in[3];
    const float* W1    = (const float*)d_in[4];
    const float* as1   = (const float*)d_in[5];
    const float* ad1   = (const float*)d_in[6];
    const float* b1    = (const float*)d_in[7];
    const float* W2    = (const float*)d_in[8];
    const float* as2   = (const float*)d_in[9];
    const float* ad2   = (const float*)d_in[10];
    const float* b2    = (const float*)d_in[11];
    const float* Wg1   = (const float*)d_in[12];
    const float* bg1   = (const float*)d_in[13];
    const float* Wg2   = (const float*)d_in[14];
    const float* bg2   = (const float*)d_in[15];
    const float* Wc1   = (const float*)d_in[16];
    const float* bc1   = (const float*)d_in[17];
    const float* Wc2   = (const float*)d_in[18];
    const float* bc2   = (const float*)d_in[19];
    float* out = (float*)d_out;

    const int* src = ei;
    const int* dst = ei + EE;

    k_prep<<<1, 256>>>(W1, as1, ad1);
    k_zero<<<(SCAN_PAD + 255) / 256, 256>>>();
    k_gemm1<<<NN / 8, 512>>>(x, W1);
    k_att1<<<(NN + 255) / 256, 256>>>(x);
    // CSR build
    k_hist<<<(EE + 255) / 256, 256>>>(dst);
    k_scan_block<<<SCAN_NB, 256>>>();
    k_scan_top<<<1, 256>>>();
    k_scan_add<<<(SCAN_PAD + 256) / 256, 256>>>();
    k_fill<<<(EE + 255) / 256, 256>>>(src, dst);
    // layer1: fused softmax + aggregate
    k_agg1<<<NN, 128>>>();
    // layer2
    k_gemm2<<<(NN + 63) / 64, 256>>>(b1, W2, as2, ad2);
    k_agg2<<<NN / 4, 128>>>();
    // pool + heads
    k_pool<<<(NN + 63) / 64, 128>>>(batch, b2);
    k_final<<<GG, 160>>>(gfeat, Wg1, bg1, Wg2, bg2, Wc1, bc1, Wc2, bc2, out);
}

// round 4
// speedup vs baseline: 2.9701x; 1.5985x over previous
#include <cuda_runtime.h>
#include <cuda_fp16.h>
#include <mma.h>
#include <math.h>

using namespace nvcuda;

#define NN 50000
#define EE 400000
#define GG 64
#define FIN 16
#define HID 128
#define HEADS 4
#define C1 512   // HEADS*HID
#define MAXD 64

#define SCAN_NB 196          // ceil(50000/256)
#define SCAN_PAD (SCAN_NB*256)

// ---------------- scratch (static device memory; no allocs) ----------------
__device__ __half   g_h1h[NN * C1];       // x@W1 (fp16)         51.2 MB
__device__ __half   g_out1h[NN * C1];     // layer1 agg (fp16)   51.2 MB
__device__ __half   g_h2h[NN * HID];      // fp16                12.8 MB
__device__ __half   g_out2h[NN * HID];    // fp16                12.8 MB
__device__ float    g_as1[NN * HEADS], g_ad1[NN * HEADS];
__device__ float    g_as2[NN], g_ad2[NN];
__device__ float    g_Ws1[FIN * HEADS], g_Wd1[FIN * HEADS];
__device__ float    g_pool[GG * HID];
__device__ float    g_cnt[GG];
// CSR by destination
__device__ int      g_deg[SCAN_PAD];
__device__ int      g_off[SCAN_PAD + 1];
__device__ int      g_cur[NN];
__device__ int      g_part[SCAN_NB];
__device__ int      g_pref[SCAN_NB];
__device__ int      g_csr_src[EE];

// ---------------- helpers ----------------
__device__ __forceinline__ float leaky(float x) { return x > 0.f ? x : 0.2f * x; }
__device__ __forceinline__ float eluf(float x)  { return x > 0.f ? x : expm1f(x); }

__device__ __forceinline__ float4 h4_to_f4(uint2 u) {
    __half2 a = *(__half2*)&u.x, b = *(__half2*)&u.y;
    float2 fa = __half22float2(a), fb = __half22float2(b);
    return make_float4(fa.x, fa.y, fb.x, fb.y);
}
__device__ __forceinline__ uint2 f4_to_h4(float4 v) {
    __half2 a = __floats2half2_rn(v.x, v.y), b = __floats2half2_rn(v.z, v.w);
    uint2 u; u.x = *(unsigned*)&a; u.y = *(unsigned*)&b; return u;
}

// ---------------- K0: fold layer1 attention vectors into W1, zero pool ----------------
__global__ void k_prep(const float* __restrict__ W1, const float* __restrict__ as1,
                       const float* __restrict__ ad1) {
    int t = threadIdx.x;
    if (t < FIN * HEADS) {
        int k = t >> 2, h = t & 3;
        float s = 0.f, d = 0.f;
        for (int c = 0; c < HID; c++) {
            float w = W1[k * C1 + h * HID + c];
            s += w * as1[h * HID + c];
            d += w * ad1[h * HID + c];
        }
        g_Ws1[t] = s; g_Wd1[t] = d;
    }
    for (int i = t; i < GG * HID; i += blockDim.x) g_pool[i] = 0.f;
    if (t < GG) g_cnt[t] = 0.f;
}

__global__ void k_zero(void) {
    int i = blockIdx.x * blockDim.x + threadIdx.x;
    if (i < SCAN_PAD) g_deg[i] = 0;
}

// ---------------- CSR build ----------------
__global__ void k_hist(const int* __restrict__ dst) {
    int e = blockIdx.x * blockDim.x + threadIdx.x;
    if (e >= EE) return;
    atomicAdd(&g_deg[dst[e]], 1);
}

__global__ void k_scan_block(void) {
    __shared__ int s[256];
    int t = threadIdx.x;
    int i = blockIdx.x * 256 + t;
    int v = g_deg[i];
    s[t] = v;
    __syncthreads();
#pragma unroll
    for (int o = 1; o < 256; o <<= 1) {
        int x = (t >= o) ? s[t - o] : 0;
        __syncthreads();
        s[t] += x;
        __syncthreads();
    }
    g_off[i] = s[t] - v;
    if (t == 255) g_part[blockIdx.x] = s[255];
}

__global__ void k_scan_top(void) {
    __shared__ int s[256];
    int t = threadIdx.x;
    int v = (t < SCAN_NB) ? g_part[t] : 0;
    s[t] = v;
    __syncthreads();
#pragma unroll
    for (int o = 1; o < 256; o <<= 1) {
        int x = (t >= o) ? s[t - o] : 0;
        __syncthreads();
        s[t] += x;
        __syncthreads();
    }
    if (t < SCAN_NB) g_pref[t] = s[t] - v;
}

__global__ void k_scan_add(void) {
    int i = blockIdx.x * blockDim.x + threadIdx.x;
    if (i > SCAN_PAD) return;
    if (i == SCAN_PAD) { g_off[i] = EE; return; }
    int p = g_off[i] + g_pref[i >> 8];
    g_off[i] = p;
    if (i < NN) g_cur[i] = p;
}

__global__ void k_fill(const int* __restrict__ src, const int* __restrict__ dst) {
    int e = blockIdx.x * blockDim.x + threadIdx.x;
    if (e >= EE) return;
    int d = dst[e];
    int p = atomicAdd(&g_cur[d], 1);
    g_csr_src[p] = src[e];
}

// ---------------- K1: h1 = x @ W1 (fp16 out) ----------------
__global__ void k_gemm1(const float* __restrict__ x, const float* __restrict__ W1) {
    __shared__ float sx[8][FIN];
    int t = threadIdx.x;
    int row0 = blockIdx.x * 8;
    if (t < 8 * FIN) {
        int r = t >> 4, k = t & 15;
        sx[r][k] = x[(row0 + r) * FIN + k];
    }
    __syncthreads();
    float w[FIN];
#pragma unroll
    for (int k = 0; k < FIN; k++) w[k] = W1[k * C1 + t];
#pragma unroll
    for (int r = 0; r < 8; r++) {
        float a = 0.f;
#pragma unroll
        for (int k = 0; k < FIN; k++) a += sx[r][k] * w[k];
        g_h1h[(row0 + r) * C1 + t] = __float2half_rn(a);
    }
}

// ---------------- K2: per-node attention logits layer1 ----------------
__global__ void k_att1(const float* __restrict__ x) {
    __shared__ float ws[FIN * HEADS], wd[FIN * HEADS];
    int t = threadIdx.x;
    if (t < FIN * HEADS) { ws[t] = g_Ws1[t]; wd[t] = g_Wd1[t]; }
    __syncthreads();
    int n = blockIdx.x * blockDim.x + t;
    if (n >= NN) return;
    float xr[FIN];
    const float4* xp = (const float4*)(x + n * FIN);
#pragma unroll
    for (int i = 0; i < 4; i++) {
        float4 v = xp[i];
        xr[i * 4 + 0] = v.x; xr[i * 4 + 1] = v.y; xr[i * 4 + 2] = v.z; xr[i * 4 + 3] = v.w;
    }
#pragma unroll
    for (int h = 0; h < HEADS; h++) {
        float s = 0.f, d = 0.f;
#pragma unroll
        for (int k = 0; k < FIN; k++) { s += xr[k] * ws[k * 4 + h]; d += xr[k] * wd[k * 4 + h]; }
        g_as1[n * 4 + h] = s;
        g_ad1[n * 4 + h] = d;
    }
}

// ---------------- K3: layer1 fused softmax + gather (block=128 thr per node) -------
__global__ void k_agg1(void) {
    __shared__ int   ssrc[MAXD];
    __shared__ float salpha[MAXD * 4];
    __shared__ float sM[4], sSinv[4], sAself[4];
    int n = blockIdx.x;
    int t = threadIdx.x;
    int w = t >> 5, lane = t & 31;
    int p0 = g_off[n], deg = g_off[n + 1] - p0;
    int degc = min(deg, MAXD);
    for (int i = t; i < degc; i += 128) ssrc[i] = g_csr_src[p0 + i];
    __syncthreads();
    {
        float adn = g_ad1[n * 4 + w];
        float vself = leaky(g_as1[n * 4 + w] + adn);
        float M = (lane == 0) ? vself : -1e30f;
        float S = (lane == 0) ? 1.f : 0.f;
        for (int i = lane; i < deg; i += 32) {
            int s = (i < MAXD) ? ssrc[i] : g_csr_src[p0 + i];
            float v = leaky(g_as1[s * 4 + w] + adn);
            float Mn = fmaxf(M, v);
            S = S * __expf(M - Mn) + __expf(v - Mn);
            M = Mn;
        }
#pragma unroll
        for (int o = 16; o > 0; o >>= 1) {
            float Mo = __shfl_xor_sync(0xffffffffu, M, o);
            float So = __shfl_xor_sync(0xffffffffu, S, o);
            float Mn = fmaxf(M, Mo);
            S = S * __expf(M - Mn) + So * __expf(Mo - Mn);
            M = Mn;
        }
        if (lane == 0) {
            float si = 1.f / S;
            sM[w] = M; sSinv[w] = si;
            sAself[w] = __expf(vself - M) * si;
        }
    }
    __syncthreads();
    for (int i = t; i < degc * 4; i += 128) {
        int e = i >> 2, h = i & 3;
        int s = ssrc[e];
        float v = leaky(g_as1[s * 4 + h] + g_ad1[n * 4 + h]);
        salpha[i] = __expf(v - sM[h]) * sSinv[h];
    }
    __syncthreads();
    int h = t >> 5;
    const uint2* h1p = (const uint2*)g_h1h;
    float Mh = sM[h], Sinvh = sSinv[h], adnh = g_ad1[n * 4 + h];
    float4 acc;
    {
        float a = sAself[h];
        float4 v = h4_to_f4(h1p[n * 128 + t]);
        acc = make_float4(a * v.x, a * v.y, a * v.z, a * v.w);
    }
    int e = 0;
    for (; e + 1 < degc; e += 2) {
        int s0 = ssrc[e], s1 = ssrc[e + 1];
        float a0 = salpha[e * 4 + h], a1 = salpha[(e + 1) * 4 + h];
        float4 v0 = h4_to_f4(h1p[s0 * 128 + t]);
        float4 v1 = h4_to_f4(h1p[s1 * 128 + t]);
        acc.x += a0 * v0.x + a1 * v1.x;
        acc.y += a0 * v0.y + a1 * v1.y;
        acc.z += a0 * v0.z + a1 * v1.z;
        acc.w += a0 * v0.w + a1 * v1.w;
    }
    for (; e < deg; e++) {
        int s; float a;
        if (e < MAXD) { s = ssrc[e]; a = salpha[e * 4 + h]; }
        else {
            s = g_csr_src[p0 + e];
            a = __expf(leaky(g_as1[s * 4 + h] + adnh) - Mh) * Sinvh;
        }
        float4 v = h4_to_f4(h1p[s * 128 + t]);
        acc.x += a * v.x; acc.y += a * v.y; acc.z += a * v.z; acc.w += a * v.w;
    }
    ((uint2*)g_out1h)[n * 128 + t] = f4_to_h4(acc);
}

// ---------------- K8: h2 = elu(out1+b1) @ W2 via WMMA, fused layer2 logits ----------------
// Block: 256 thr (8 warps), tile M=64, N=128(all), K staged 64.
// Warp (wm 0..3, wn 0..1) computes rows wm*16.., cols wn*64.. (4 n-frags).
#define AS_LD 72
#define BS_LD 136
#define CS_LD 136
__global__ void k_gemm2w(const float* __restrict__ b1, const float* __restrict__ W2,
                         const float* __restrict__ as2, const float* __restrict__ ad2) {
    __shared__ __align__(16) char sbuf[64 * CS_LD * 4];   // 34816 B, aliased
    __half (*As)[AS_LD] = (__half(*)[AS_LD])sbuf;
    __half (*Bs)[BS_LD] = (__half(*)[BS_LD])(sbuf + 64 * AS_LD * 2);
    float  (*Cs)[CS_LD] = (float(*)[CS_LD])sbuf;
    __shared__ float sb1[C1];
    __shared__ float sa[HID], sd[HID];

    int t = threadIdx.x;
    int wid = t >> 5, lane = t & 31;
    int wm = wid >> 1, wn = wid & 1;
    int row0 = blockIdx.x * 64;

    for (int i = t; i < C1; i += 256) sb1[i] = b1[i];
    if (t < HID) { sa[t] = as2[t]; sd[t] = ad2[t]; }
    __syncthreads();

    wmma::fragment<wmma::accumulator, 16, 16, 16, float> acc[4];
#pragma unroll
    for (int i = 0; i < 4; i++) wmma::fill_fragment(acc[i], 0.f);

    int r = t >> 2, cseg = t & 3;        // As loader: 4 threads/row, 4 uint2 each

    for (int kt = 0; kt < C1; kt += 64) {
        // --- load A tile: elu(out1h + b1) -> fp16 ---
        int row = row0 + r;
        if (row < NN) {
            const uint2* srcp = (const uint2*)&g_out1h[row * C1 + kt];
#pragma unroll
            for (int j = 0; j < 4; j++) {
                int c4 = cseg * 4 + j;             // uint2 index 0..15
                float4 v = h4_to_f4(srcp[c4]);
                int cb = kt + c4 * 4;
                v.x = eluf(v.x + sb1[cb + 0]);
                v.y = eluf(v.y + sb1[cb + 1]);
                v.z = eluf(v.z + sb1[cb + 2]);
                v.w = eluf(v.w + sb1[cb + 3]);
                *(uint2*)&As[r][c4 * 4] = f4_to_h4(v);
            }
        } else {
            uint2 z; z.x = 0u; z.y = 0u;
#pragma unroll
            for (int j = 0; j < 4; j++) *(uint2*)&As[r][(cseg * 4 + j) * 4] = z;
        }
        // --- load B tile: W2 fp32 -> fp16 ---
#pragma unroll
        for (int j = 0; j < 8; j++) {
            int idx = t + j * 256;                 // float4 idx 0..2047
            int rr = idx >> 5, cc = idx & 31;      // 32 float4 per row
            float4 w = *(const float4*)&W2[(kt + rr) * HID + cc * 4];
            *(uint2*)&Bs[rr][cc * 4] = f4_to_h4(w);
        }
        __syncthreads();
#pragma unroll
        for (int kk = 0; kk < 4; kk++) {
            wmma::fragment<wmma::matrix_a, 16, 16, 16, __half, wmma::row_major> af;
            wmma::load_matrix_sync(af, &As[wm * 16][kk * 16], AS_LD);
#pragma unroll
            for (int nf = 0; nf < 4; nf++) {
                wmma::fragment<wmma::matrix_b, 16, 16, 16, __half, wmma::row_major> bf;
                wmma::load_matrix_sync(bf, &Bs[kk * 16][wn * 64 + nf * 16], BS_LD);
                wmma::mma_sync(acc[nf], af, bf, acc[nf]);
            }
        }
        __syncthreads();
    }
    // park accumulators (aliases As/Bs — all reads done)
#pragma unroll
    for (int nf = 0; nf < 4; nf++)
        wmma::store_matrix_sync(&Cs[wm * 16][wn * 64 + nf * 16], acc[nf], CS_LD,
                                wmma::mem_row_major);
    __syncthreads();
    // epilogue A: write h2h (fp16). 4 threads/row, 8 uint2 each.
    {
        int r2 = t >> 2, seg = t & 3;
        int row = row0 + r2;
        if (row < NN) {
            uint2* dstp = (uint2*)&g_h2h[row * HID];
#pragma unroll
            for (int j = 0; j < 8; j++) {
                int c4 = seg * 8 + j;              // uint2 idx 0..31
                float4 v = make_float4(Cs[r2][c4 * 4], Cs[r2][c4 * 4 + 1],
                                       Cs[r2][c4 * 4 + 2], Cs[r2][c4 * 4 + 3]);
                dstp[c4] = f4_to_h4(v);
            }
        }
    }
    // epilogue B: attention logits. warp handles 8 rows.
#pragma unroll
    for (int i = 0; i < 8; i++) {
        int rI = wid * 8 + i;
        int row = row0 + rI;
        float s = 0.f, d = 0.f;
#pragma unroll
        for (int c = 0; c < 4; c++) {
            float v = Cs[rI][lane + c * 32];
            s += v * sa[lane + c * 32];
            d += v * sd[lane + c * 32];
        }
#pragma unroll
        for (int o = 16; o > 0; o >>= 1) {
            s += __shfl_xor_sync(0xffffffffu, s, o);
            d += __shfl_xor_sync(0xffffffffu, d, o);
        }
        if (lane == 0 && row < NN) { g_as2[row] = s; g_ad2[row] = d; }
    }
}

// ---------------- K12: layer2 fused softmax + gather (warp per node) -------
__global__ void k_agg2(void) {
    __shared__ int   ssrc[4][MAXD];
    __shared__ float salpha[4][MAXD];
    int t = threadIdx.x;
    int w = t >> 5, lane = t & 31;
    int n = blockIdx.x * 4 + w;
    int p0 = g_off[n], deg = g_off[n + 1] - p0;
    int degc = min(deg, MAXD);
    for (int i = lane; i < degc; i += 32) ssrc[w][i] = g_csr_src[p0 + i];
    __syncwarp();
    float adn = g_ad2[n];
    float vself = leaky(g_as2[n] + adn);
    float M = (lane == 0) ? vself : -1e30f;
    float S = (lane == 0) ? 1.f : 0.f;
    for (int i = lane; i < deg; i += 32) {
        int s = (i < MAXD) ? ssrc[w][i] : g_csr_src[p0 + i];
        float v = leaky(g_as2[s] + adn);
        float Mn = fmaxf(M, v);
        S = S * __expf(M - Mn) + __expf(v - Mn);
        M = Mn;
    }
#pragma unroll
    for (int o = 16; o > 0; o >>= 1) {
        float Mo = __shfl_xor_sync(0xffffffffu, M, o);
        float So = __shfl_xor_sync(0xffffffffu, S, o);
        float Mn = fmaxf(M, Mo);
        S = S * __expf(M - Mn) + So * __expf(Mo - Mn);
        M = Mn;
    }
    float Sinv = 1.f / S;
    float aself = __expf(vself - M) * Sinv;
    for (int i = lane; i < degc; i += 32) {
        int s = ssrc[w][i];
        salpha[w][i] = __expf(leaky(g_as2[s] + adn) - M) * Sinv;
    }
    __syncwarp();
    const uint2* h2p = (const uint2*)g_h2h;
    float4 acc;
    {
        float4 v = h4_to_f4(h2p[n * 32 + lane]);
        acc = make_float4(aself * v.x, aself * v.y, aself * v.z, aself * v.w);
    }
    int e = 0;
    for (; e + 1 < degc; e += 2) {
        int s0 = ssrc[w][e], s1 = ssrc[w][e + 1];
        float a0 = salpha[w][e], a1 = salpha[w][e + 1];
        float4 v0 = h4_to_f4(h2p[s0 * 32 + lane]);
        float4 v1 = h4_to_f4(h2p[s1 * 32 + lane]);
        acc.x += a0 * v0.x + a1 * v1.x;
        acc.y += a0 * v0.y + a1 * v1.y;
        acc.z += a0 * v0.z + a1 * v1.z;
        acc.w += a0 * v0.w + a1 * v1.w;
    }
    for (; e < deg; e++) {
        int s; float a;
        if (e < MAXD) { s = ssrc[w][e]; a = salpha[w][e]; }
        else {
            s = g_csr_src[p0 + e];
            a = __expf(leaky(g_as2[s] + adn) - M) * Sinv;
        }
        float4 v = h4_to_f4(h2p[s * 32 + lane]);
        acc.x += a * v.x; acc.y += a * v.y; acc.z += a * v.z; acc.w += a * v.w;
    }
    ((uint2*)g_out2h)[n * 32 + lane] = f4_to_h4(acc);
}

// ---------------- K13: elu(out2+b2) + segmented mean-pool ----------------
__global__ void k_pool(const int* __restrict__ batch, const float* __restrict__ b2) {
    int c = threadIdx.x;
    int n0 = blockIdx.x * 64;
    float b2c = b2[c];
    int curg = -1;
    float acc = 0.f;
    int cnt = 0;
    for (int i = 0; i < 64; i++) {
        int n = n0 + i;
        if (n >= NN) break;
        int g = batch[n];
        if (g != curg) {
            if (curg >= 0) {
                atomicAdd(&g_pool[curg * HID + c], acc);
                if (c == 0) atomicAdd(&g_cnt[curg], (float)cnt);
            }
            curg = g; acc = 0.f; cnt = 0;
        }
        float v = __half2float(g_out2h[n * HID + c]) + b2c;
        acc += eluf(v);
        cnt++;
    }
    if (curg >= 0) {
        atomicAdd(&g_pool[curg * HID + c], acc);
        if (c == 0) atomicAdd(&g_cnt[curg], (float)cnt);
    }
}

// ---------------- K14: graph MLP + classifier ----------------
__global__ void k_final(const float* __restrict__ gfeat,
                        const float* __restrict__ Wg1, const float* __restrict__ bg1,
                        const float* __restrict__ Wg2, const float* __restrict__ bg2,
                        const float* __restrict__ Wc1, const float* __restrict__ bc1,
                        const float* __restrict__ Wc2, const float* __restrict__ bc2,
                        float* __restrict__ out) {
    int g = blockIdx.x;
    int t = threadIdx.x;
    __shared__ float z[HID + 32];
    __shared__ float hg[32];
    __shared__ float gfr[10];
    __shared__ float t1[128];
    if (t < 10) gfr[t] = gfeat[g * 10 + t];
    __syncthreads();
    if (t < 32) {
        float s = bg1[t];
#pragma unroll
        for (int k = 0; k < 10; k++) s += gfr[k] * Wg1[k * 32 + t];
        hg[t] = fmaxf(s, 0.f);
    }
    if (t < HID) {
        float inv = 1.f / fmaxf(g_cnt[g], 1.f);
        z[t] = g_pool[g * HID + t] * inv;
    }
    __syncthreads();
    if (t < 32) {
        float s = bg2[t];
#pragma unroll
        for (int k = 0; k < 32; k++) s += hg[k] * Wg2[k * 32 + t];
        z[HID + t] = s;
    }
    __syncthreads();
    if (t < 128) {
        float s = bc1[t];
        for (int k = 0; k < HID + 32; k++) s += z[k] * Wc1[k * 128 + t];
        t1[t] = fmaxf(s, 0.f);
    }
    __syncthreads();
    if (t < 6) {
        float s = bc2[t];
        for (int k = 0; k < 128; k++) s += t1[k] * Wc2[k * 6 + t];
        out[g * 6 + t] = s;
    }
}

// ---------------- launch ----------------
extern "C" void kernel_launch(void* const* d_in, const int* in_sizes, int n_in,
                              void* d_out, int out_size) {
    const float* x     = (const float*)d_in[0];
    const int*   ei    = (const int*)d_in[1];
    const int*   batch = (const int*)d_in[2];
    const float* gfeat = (const float*)d_in[3];
    const float* W1    = (const float*)d_in[4];
    const float* as1   = (const float*)d_in[5];
    const float* ad1   = (const float*)d_in[6];
    const float* b1    = (const float*)d_in[7];
    const float* W2    = (const float*)d_in[8];
    const float* as2   = (const float*)d_in[9];
    const float* ad2   = (const float*)d_in[10];
    const float* b2    = (const float*)d_in[11];
    const float* Wg1   = (const float*)d_in[12];
    const float* bg1   = (const float*)d_in[13];
    const float* Wg2   = (const float*)d_in[14];
    const float* bg2   = (const float*)d_in[15];
    const float* Wc1   = (const float*)d_in[16];
    const float* bc1   = (const float*)d_in[17];
    const float* Wc2   = (const float*)d_in[18];
    const float* bc2   = (const float*)d_in[19];
    float* out = (float*)d_out;

    const int* src = ei;
    const int* dst = ei + EE;

    k_prep<<<1, 256>>>(W1, as1, ad1);
    k_zero<<<(SCAN_PAD + 255) / 256, 256>>>();
    k_gemm1<<<NN / 8, 512>>>(x, W1);
    k_att1<<<(NN + 255) / 256, 256>>>(x);
    // CSR build
    k_hist<<<(EE + 255) / 256, 256>>>(dst);
    k_scan_block<<<SCAN_NB, 256>>>();
    k_scan_top<<<1, 256>>>();
    k_scan_add<<<(SCAN_PAD + 256) / 256, 256>>>();
    k_fill<<<(EE + 255) / 256, 256>>>(src, dst);
    // layer1: fused softmax + aggregate
    k_agg1<<<NN, 128>>>();
    // layer2: WMMA gemm + fused logits
    k_gemm2w<<<(NN + 63) / 64, 256>>>(b1, W2, as2, ad2);
    k_agg2<<<NN / 4, 128>>>();
    // pool + heads
    k_pool<<<(NN + 63) / 64, 128>>>(batch, b2);
    k_final<<<GG, 160>>>(gfeat, Wg1, bg1, Wg2, bg2, Wc1, bc1, Wc2, bc2, out);
}